// round 12
// baseline (speedup 1.0000x reference)
#include <cuda_runtime.h>
#include <cuda_fp16.h>

#define NUM_USERS 80000
#define NUM_ITEMS 40000
#define NUM_NODES 120000
#define DIM       64
#define NE        (NUM_NODES * DIM)     // 7,680,000
#define NE4       (NE / 4)              // 1,920,000
#define NU4       (NUM_USERS * DIM / 4) // 1,280,000
#define ALPHA     0.8f
#define MAX_EPATH 2000000
#define WEDGES    128                    // edges per warp (proven config)
#define QE        (WEDGES / 4)           // edges per quarter-warp (32)

// ---------------- scratch (device globals; zero-initialized .bss) ----------
__device__ __align__(256) float   g_t[NE];        // fp32 accumulator (zero at entry, restored at exit)
__device__ __align__(256) __half2 g_hin[NE / 2];  // fp16 copy of [user_emb; item_emb]
__device__ __align__(256) __half2 g_h0[NE / 2];   // e0 (fp16)
__device__ __align__(256) __half2 g_h1[NE / 2];   // e1 (fp16)
__device__ __align__(256) __half2 g_h2[NE / 2];   // e2 (fp16)
__device__ __align__(256) float   g_softv[MAX_EPATH];
__device__ __align__(256) float   g_rowsum[NUM_NODES];
__device__ __align__(256) float   g_thetaw[8];

// ---------------- packed f32x2 helpers (sm_103a) ----------------------------
__device__ __forceinline__ unsigned long long pack2(float lo, float hi)
{
    unsigned long long out;
    asm("mov.b64 %0, {%1, %2};" : "=l"(out)
        : "r"(__float_as_uint(lo)), "r"(__float_as_uint(hi)));
    return out;
}
__device__ __forceinline__ void unpack2(unsigned long long in, float& lo, float& hi)
{
    unsigned int a, b;
    asm("mov.b64 {%0, %1}, %2;" : "=r"(a), "=r"(b) : "l"(in));
    lo = __uint_as_float(a); hi = __uint_as_float(b);
}
#define FMA_F32X2(acc, x, f2) \
    asm("fma.rn.f32x2 %0, %1, %2, %0;" : "+l"(acc) : "l"(x), "l"(f2))

// ---------------- fused prologue: cvt + rowsum zero + theta softmax --------
__global__ __launch_bounds__(256) void k_prologue(
    const float4* __restrict__ U, const float4* __restrict__ I,
    __half2* __restrict__ H, float4* __restrict__ rs4,
    const float* __restrict__ theta, float* __restrict__ tw, int n_theta)
{
    int i = blockIdx.x * blockDim.x + threadIdx.x;
    if (i < NE4) {
        float4 v = (i < NU4) ? U[i] : I[i - NU4];
        H[2 * i]     = __floats2half2_rn(v.x, v.y);
        H[2 * i + 1] = __floats2half2_rn(v.z, v.w);
    }
    if (i < NUM_NODES / 4)
        rs4[i] = make_float4(0.f, 0.f, 0.f, 0.f);
    if (i == 0) {
        float m = -1e30f;
        for (int k = 0; k < n_theta; k++) m = fmaxf(m, theta[k]);
        float s = 0.f; float w[8];
        for (int k = 0; k < n_theta; k++) { w[k] = expf(theta[k] - m); s += w[k]; }
        for (int k = 0; k < n_theta; k++) tw[k] = w[k] / s;
    }
}

// ---------------- path pass: exp(counts @ theta_w), row sums ---------------
__global__ __launch_bounds__(256) void k_path1(
    const int* __restrict__ p_row, const float* __restrict__ p_counts,
    const float* __restrict__ tw, float* __restrict__ softv,
    float* __restrict__ rowsum, int n)
{
    const int t = blockIdx.x * blockDim.x + threadIdx.x;   // edge pair index
    const int e0 = 2 * t;
    if (e0 >= n) return;
    const float w0 = tw[0], w1 = tw[1], w2 = tw[2],
                w3 = tw[3], w4 = tw[4], w5 = tw[5];
    const float4* src = (const float4*)(p_counts + (size_t)e0 * 6);
    float4 a = __ldcs(src);
    float4 b = __ldcs(src + 1);
    float4 c = __ldcs(src + 2);
    float v0 = a.x * w0;
    v0 = fmaf(a.y, w1, v0); v0 = fmaf(a.z, w2, v0);
    v0 = fmaf(a.w, w3, v0); v0 = fmaf(b.x, w4, v0);
    v0 = fmaf(b.y, w5, v0);
    float ev0 = expf(v0);
    atomicAdd(&rowsum[p_row[e0]], ev0);
    if (e0 + 1 < n) {
        float v1 = b.z * w0;
        v1 = fmaf(b.w, w1, v1); v1 = fmaf(c.x, w2, v1);
        v1 = fmaf(c.y, w3, v1); v1 = fmaf(c.z, w4, v1);
        v1 = fmaf(c.w, w5, v1);
        float ev1 = expf(v1);
        *(float2*)(softv + e0) = make_float2(ev0, ev1);
        atomicAdd(&rowsum[p_row[e0 + 1]], ev1);
    } else {
        softv[e0] = ev0;
    }
}

// ---------------- vector reduction flush (packed accumulators) -------------
__device__ __forceinline__ void flush_packed(
    float* __restrict__ y, int row, int ql,
    unsigned long long a01, unsigned long long a23,
    unsigned long long a45, unsigned long long a67)
{
    float f0, f1, f2, f3, f4, f5, f6, f7;
    unpack2(a01, f0, f1); unpack2(a23, f2, f3);
    unpack2(a45, f4, f5); unpack2(a67, f6, f7);
    float* p = y + row * DIM + ql * 8;
    asm volatile("red.global.add.v4.f32 [%0], {%1,%2,%3,%4};"
                 :: "l"(p), "f"(f0), "f"(f1), "f"(f2), "f"(f3) : "memory");
    asm volatile("red.global.add.v4.f32 [%0], {%1,%2,%3,%4};"
                 :: "l"(p + 4), "f"(f4), "f"(f5), "f"(f6), "f"(f7) : "memory");
}

// ============================================================================
// Quarter-warp fp16 SpMM body, depth-1 gather prefetch, packed FFMA2 math.
// Warp = 4 quarters x 8 lanes; each quarter owns a contiguous edge sub-chunk;
// each lane owns 8 dims (one LDG.128 of fp16 per edge per lane).
// Rows sorted -> register accumulation, vector-red flush on row change.
// ============================================================================
__device__ __forceinline__ void spmm_chunk(
    const int* __restrict__ rows, const int* __restrict__ cols,
    const float* __restrict__ vals,
    int base, int cnt, float scale,
    const uint4* __restrict__ x, float* __restrict__ y,
    float4* __restrict__ meta, int lane)
{
    for (int i = lane; i < cnt; i += 32) {
        int gi = base + i;
        meta[i] = make_float4(__int_as_float(__ldcs(rows + gi)),
                              __int_as_float(__ldcs(cols + gi)),
                              __ldcs(vals + gi) * scale, 0.f);
    }
    __syncwarp();
    const int ql   = lane & 7;
    const int qbeg = (lane >> 3) * QE;
    const int qend = min(qbeg + QE, cnt);
    if (qbeg >= qend) return;

    unsigned long long a01 = 0ull, a23 = 0ull, a45 = 0ull, a67 = 0ull;
    int cur = -1;

    // prime prefetch
    float4 md = meta[qbeg];
    uint4  hv = x[(size_t)__float_as_int(md.y) * 8 + ql];

    for (int j = qbeg; j < qend; j++) {
        // prefetch next edge's gather before consuming this one
        float4 mdn = md; uint4 hvn = hv;
        if (j + 1 < qend) {
            mdn = meta[j + 1];
            hvn = x[(size_t)__float_as_int(mdn.y) * 8 + ql];
        }
        int rj = __float_as_int(md.x);
        if (rj != cur) {
            if (cur >= 0) flush_packed(y, cur, ql, a01, a23, a45, a67);
            cur = rj;
            a01 = 0ull; a23 = 0ull; a45 = 0ull; a67 = 0ull;
        }
        unsigned long long ff = pack2(md.z, md.z);
        float2 p0 = __half22float2(*(const __half2*)&hv.x);
        float2 p1 = __half22float2(*(const __half2*)&hv.y);
        float2 p2 = __half22float2(*(const __half2*)&hv.z);
        float2 p3 = __half22float2(*(const __half2*)&hv.w);
        FMA_F32X2(a01, pack2(p0.x, p0.y), ff);
        FMA_F32X2(a23, pack2(p1.x, p1.y), ff);
        FMA_F32X2(a45, pack2(p2.x, p2.y), ff);
        FMA_F32X2(a67, pack2(p3.x, p3.y), ff);
        md = mdn; hv = hvn;
    }
    flush_packed(y, cur, ql, a01, a23, a45, a67);
}

// ---------------- fused pos+neg layer SpMM ----------------------------------
__global__ __launch_bounds__(256) void k_spmm_dual(
    const int* __restrict__ prow, const int* __restrict__ pcol,
    const float* __restrict__ pval, int npos, int pos_blocks,
    const int* __restrict__ nrow, const int* __restrict__ ncol,
    const float* __restrict__ nval, int nneg,
    const uint4* __restrict__ x, float* __restrict__ y)
{
    __shared__ float4 meta[8][WEDGES];
    const int wslot = threadIdx.x >> 5;
    const int lane  = threadIdx.x & 31;

    const bool isneg = (blockIdx.x >= pos_blocks);
    const int  bid   = isneg ? (blockIdx.x - pos_blocks) : blockIdx.x;
    const int* rows  = isneg ? nrow : prow;
    const int* cols  = isneg ? ncol : pcol;
    const float* vals = isneg ? nval : pval;
    const int  n     = isneg ? nneg : npos;
    const float scale = isneg ? -ALPHA : 1.0f;

    const int base = (bid * 8 + wslot) * WEDGES;
    if (base >= n) return;
    const int cnt = min(WEDGES, n - base);
    spmm_chunk(rows, cols, vals, base, cnt, scale, x, y, meta[wslot], lane);
}

// ---------------- path SpMM (unnormalized; same body as dual) ---------------
__global__ __launch_bounds__(256) void k_spmm_path(
    const int* __restrict__ rows, const int* __restrict__ cols,
    const float* __restrict__ evals, int n,
    const uint4* __restrict__ x, float* __restrict__ y)
{
    __shared__ float4 meta[8][WEDGES];
    const int wslot = threadIdx.x >> 5;
    const int lane  = threadIdx.x & 31;
    const int base  = (blockIdx.x * 8 + wslot) * WEDGES;
    if (base >= n) return;
    const int cnt = min(WEDGES, n - base);
    spmm_chunk(rows, cols, evals, base, cnt, 1.0f, x, y, meta[wslot], lane);
}

// ---------------- e0 epilogue: e0 = t/rowsum; H0 = half(e0); t = a*e0 -------
__global__ void k_init(float4* __restrict__ T, __half2* __restrict__ H,
                       const float* __restrict__ rowsum, int n4)
{
    int i = blockIdx.x * blockDim.x + threadIdx.x;
    if (i >= n4) return;
    const float inv = 1.f / (rowsum[i >> 4] + 1e-12f);   // 16 float4s per node row
    float4 t = T[i];
    t.x *= inv; t.y *= inv; t.z *= inv; t.w *= inv;
    H[2 * i]     = __floats2half2_rn(t.x, t.y);
    H[2 * i + 1] = __floats2half2_rn(t.z, t.w);
    T[i] = make_float4(ALPHA * t.x, ALPHA * t.y, ALPHA * t.z, ALPHA * t.w);
}

// ---------------- layer epilogue: e_new = t; Hnew = half(t); t = a*t --------
__global__ void k_layer(float4* __restrict__ T, __half2* __restrict__ Hnew, int n4)
{
    int i = blockIdx.x * blockDim.x + threadIdx.x;
    if (i >= n4) return;
    float4 t = T[i];
    Hnew[2 * i]     = __floats2half2_rn(t.x, t.y);
    Hnew[2 * i + 1] = __floats2half2_rn(t.z, t.w);
    T[i] = make_float4(ALPHA * t.x, ALPHA * t.y, ALPHA * t.z, ALPHA * t.w);
}

// ---------------- final: out = (H0 + H1 + H2 + t)/4; t = 0 ------------------
__global__ void k_final(float4* __restrict__ T,
                        const __half2* __restrict__ H0,
                        const __half2* __restrict__ H1,
                        const __half2* __restrict__ H2,
                        float4* __restrict__ O, int n4)
{
    int i = blockIdx.x * blockDim.x + threadIdx.x;
    if (i >= n4) return;
    float4 t = T[i];                                  // t == e3
    float2 a01 = __half22float2(H0[2 * i]);
    float2 a23 = __half22float2(H0[2 * i + 1]);
    float2 b01 = __half22float2(H1[2 * i]);
    float2 b23 = __half22float2(H1[2 * i + 1]);
    float2 c01 = __half22float2(H2[2 * i]);
    float2 c23 = __half22float2(H2[2 * i + 1]);
    float4 o;
    o.x = (a01.x + b01.x + c01.x + t.x) * 0.25f;
    o.y = (a01.y + b01.y + c01.y + t.y) * 0.25f;
    o.z = (a23.x + b23.x + c23.x + t.z) * 0.25f;
    o.w = (a23.y + b23.y + c23.y + t.w) * 0.25f;
    O[i] = o;
    T[i] = make_float4(0.f, 0.f, 0.f, 0.f);   // restore zero-at-entry invariant
}

// ---------------------------------------------------------------------------
extern "C" void kernel_launch(void* const* d_in, const int* in_sizes, int n_in,
                              void* d_out, int out_size)
{
    const float* user_emb = (const float*)d_in[0];
    const float* item_emb = (const float*)d_in[1];
    const float* theta    = (const float*)d_in[2];
    const int*   pos_row  = (const int*)d_in[3];
    const int*   pos_col  = (const int*)d_in[4];
    const float* pos_val  = (const float*)d_in[5];
    const int*   neg_row  = (const int*)d_in[6];
    const int*   neg_col  = (const int*)d_in[7];
    const float* neg_val  = (const float*)d_in[8];
    const int*   p_row    = (const int*)d_in[9];
    const int*   p_col    = (const int*)d_in[10];
    const float* p_counts = (const float*)d_in[11];

    const int n_pos  = in_sizes[3];
    const int n_neg  = in_sizes[6];
    int n_path = in_sizes[9];
    if (n_path > MAX_EPATH) n_path = MAX_EPATH;
    const int n_theta = in_sizes[2] < 8 ? in_sizes[2] : 8;

    float *pt, *psv, *prs, *ptw;
    __half2 *hin, *h0, *h1, *h2;
    cudaGetSymbolAddress((void**)&pt,  g_t);
    cudaGetSymbolAddress((void**)&hin, g_hin);
    cudaGetSymbolAddress((void**)&h0,  g_h0);
    cudaGetSymbolAddress((void**)&h1,  g_h1);
    cudaGetSymbolAddress((void**)&h2,  g_h2);
    cudaGetSymbolAddress((void**)&psv, g_softv);
    cudaGetSymbolAddress((void**)&prs, g_rowsum);
    cudaGetSymbolAddress((void**)&ptw, g_thetaw);

    const int TB = 256;

    // fused prologue: fp16 input table + rowsum zero + theta softmax
    k_prologue<<<(NE4 + TB - 1) / TB, TB>>>((const float4*)user_emb,
                                            (const float4*)item_emb, hin,
                                            (float4*)prs, theta, ptw, n_theta);

    // path edge weights (exp + rowsums); normalization deferred to k_init
    {
        int pairs = (n_path + 1) / 2;
        k_path1<<<(pairs + TB - 1) / TB, TB>>>(p_row, p_counts, ptw, psv, prs, n_path);
    }

    // t = unnormalized path gather sums
    {
        int warps = (n_path + WEDGES - 1) / WEDGES;
        k_spmm_path<<<(warps + 7) / 8, TB>>>(p_row, p_col, psv, n_path,
                                             (const uint4*)hin, pt);
    }

    // e0 = t/rowsum; H0 = half(e0); t = a*e0
    k_init<<<(NE4 + TB - 1) / TB, TB>>>((float4*)pt, h0, prs, NE4);

    const int pos_blocks = ((n_pos + WEDGES - 1) / WEDGES + 7) / 8;
    const int neg_blocks = ((n_neg + WEDGES - 1) / WEDGES + 7) / 8;
    const int dual_grid  = pos_blocks + neg_blocks;

    // layer 1: t(=a*e0) += pos(H0) - a*neg(H0)  ->  t == e1
    k_spmm_dual<<<dual_grid, TB>>>(pos_row, pos_col, pos_val, n_pos, pos_blocks,
                                   neg_row, neg_col, neg_val, n_neg,
                                   (const uint4*)h0, pt);
    k_layer<<<(NE4 + TB - 1) / TB, TB>>>((float4*)pt, h1, NE4);

    // layer 2
    k_spmm_dual<<<dual_grid, TB>>>(pos_row, pos_col, pos_val, n_pos, pos_blocks,
                                   neg_row, neg_col, neg_val, n_neg,
                                   (const uint4*)h1, pt);
    k_layer<<<(NE4 + TB - 1) / TB, TB>>>((float4*)pt, h2, NE4);

    // layer 3 + fused final mean (t == e3 after the dual)
    k_spmm_dual<<<dual_grid, TB>>>(pos_row, pos_col, pos_val, n_pos, pos_blocks,
                                   neg_row, neg_col, neg_val, n_neg,
                                   (const uint4*)h2, pt);
    k_final<<<(NE4 + TB - 1) / TB, TB>>>((float4*)pt, h0, h1, h2,
                                         (float4*)d_out, NE4);
}